// round 12
// baseline (speedup 1.0000x reference)
#include <cuda_runtime.h>
#include <stdint.h>
#include <math.h>

#define MAXB 16
#define MAXH 32
#define TPB 256
#define NWARP (TPB / 32)
#define NCTA 1184
#define CHLOG 8u
#define CH (1u << CHLOG)        // 256-float column chunks
#define SBUF_N (CH + 8u)        // + window slack

__device__ __forceinline__ void st_cs(float4* p, float4 v) {
    asm volatile("st.global.cs.v4.f32 [%0], {%1,%2,%3,%4};"
                 :: "l"(p), "f"(v.x), "f"(v.y), "f"(v.z), "f"(v.w) : "memory");
}
__device__ __forceinline__ void cp_async16(unsigned saddr, const void* gptr) {
    asm volatile("cp.async.ca.shared.global [%0], [%1], 16;"
                 :: "r"(saddr), "l"(gptr));
}
#define CP_COMMIT() asm volatile("cp.async.commit_group;" ::: "memory")
#define CP_WAIT(n)  asm volatile("cp.async.wait_group %0;" :: "n"(n) : "memory")

// magic division q = (x*m)>>sh == x/d, valid x < 2^31, d >= 1
__device__ __forceinline__ void magic_u32(unsigned d, unsigned& m, unsigned& sh) {
    unsigned k = (d > 1u) ? (32u - __clz(d - 1u)) : 0u;
    unsigned long long two = 1ull << (31 + k);
    m = (unsigned)((two + d - 1ull) / d);
    sh = 31u + k;
}

// Unit = (source row, 256-float column chunk) fanned out to all H heads.
// Near-uniform unit size (~16KB written) -> balanced static interleave.
// Each source float staged into SMEM exactly once (keeps L2 reads ~40MB).
__global__ void __launch_bounds__(TPB)
fused_kernel(const float* __restrict__ mask, const int* __restrict__ seq,
             const int* __restrict__ nh, float* __restrict__ out,
             unsigned out_size, unsigned S, int B) {
    __shared__ unsigned sh_s[MAXB], sh_s2[MAXB];
    __shared__ unsigned sh_boff[MAXB];
    __shared__ unsigned sh_up[MAXB + 1];     // unit prefix per batch
    __shared__ unsigned sh_cpr[MAXB];        // chunks per row
    __shared__ unsigned sh_m[MAXB], sh_sh[MAXB]; // magic for /cpr
    __shared__ unsigned sh_H, sh_units;
    __shared__ __align__(16) float sbuf[2][SBUF_N];

    const unsigned t = threadIdx.x;
    const unsigned lane = t & 31u;
    const unsigned wid  = t >> 5;

    if (t < (unsigned)B) sh_s[t] = (unsigned)seq[t];
    if (t == 0) {
        unsigned H = nh ? (unsigned)(*nh) : 16u;
        if (H > MAXH) H = MAXH;
        if (H < 1u) H = 1u;
        sh_H = H;
    }
    __syncthreads();
    if (t == 0) {
        unsigned acc = 0, uacc = 0, H = sh_H;
        for (int i = 0; i < B; ++i) {
            unsigned s = sh_s[i];
            unsigned cpr = (s + CH - 1u) >> CHLOG;
            sh_s2[i] = s * s;
            sh_boff[i] = acc;
            sh_cpr[i] = cpr;
            sh_up[i] = uacc;
            magic_u32(cpr, sh_m[i], sh_sh[i]);
            acc += H * s * s;
            uacc += s * cpr;
        }
        sh_up[B] = uacc;
        sh_units = uacc;
    }
    __syncthreads();

    const unsigned H = sh_H;
    const unsigned totalUnits = sh_units;

    // decode unit id -> (batch i, row r, chunk start c0, slice len)
    auto decode = [&](unsigned u, unsigned& i, unsigned& r,
                      unsigned& c0, unsigned& len) {
        unsigned ii = 0;
        while (ii + 1u < (unsigned)B && u >= sh_up[ii + 1u]) ++ii;
        unsigned rem = u - sh_up[ii];           // < s*cpr <= 16376
        unsigned cpr = sh_cpr[ii];
        unsigned rr = (unsigned)(((unsigned long long)rem * sh_m[ii]) >> sh_sh[ii]);
        unsigned ch = rem - rr * cpr;
        unsigned s = sh_s[ii];
        i = ii; r = rr; c0 = ch << CHLOG;
        unsigned l = s - c0; if (l > CH) l = CH;
        len = l;
    };
    // stage slice (len+4 floats, 16B-aligned source) into sbuf[buf].
    // Overread past row end stays inside the mask allocation (proof:
    // worst offset (i*S + r)*S + c0 + 4*nld <= B*S*S for S >= 2048).
    auto stage = [&](unsigned buf, unsigned i, unsigned r, unsigned c0,
                     unsigned len) {
        const float4* src4 = reinterpret_cast<const float4*>(
            mask + ((size_t)i * S + r) * (size_t)S + c0);
        unsigned sb = (unsigned)__cvta_generic_to_shared(&sbuf[buf][0]);
        const unsigned nld = (len + 7u) >> 2;
        if (t < nld) cp_async16(sb + 16u * t, src4 + t);
    };

    unsigned u = blockIdx.x;
    if (u >= totalUnits) return;

    unsigned ci, cr, cc0, clen;
    decode(u, ci, cr, cc0, clen);
    stage(0, ci, cr, cc0, clen);
    CP_COMMIT();
    unsigned cur = 0;

    for (; u < totalUnits; u += gridDim.x) {
        const unsigned un = u + gridDim.x;
        unsigned ni = 0, nr = 0, nc0 = 0, nlen = 0;
        if (un < totalUnits) {
            decode(un, ni, nr, nc0, nlen);
            stage(cur ^ 1u, ni, nr, nc0, nlen);  // overlaps fan-out below
            CP_COMMIT();
            CP_WAIT(1);
        } else {
            CP_WAIT(0);
        }
        __syncthreads();

        const unsigned s = sh_s[ci];
        const unsigned s2 = sh_s2[ci];
        const unsigned base = sh_boff[ci] + cr * s + cc0;
        const float* sb = sbuf[cur];

        // ---- warp-per-head fan-out of the staged slice ----
        for (unsigned h = wid; h < H; h += NWARP) {
            unsigned off = base + h * s2;
            if (off >= out_size) continue;
            unsigned olen = clen;
            if (olen > out_size - off) olen = out_size - off;

            unsigned lead = (4u - (off & 3u)) & 3u;   // align dst to 16B
            if (lead > olen) lead = olen;
            if (lane < lead) out[off + lane] = sb[lane];

            const unsigned n4 = (olen - lead) >> 2;
            float4* vd = reinterpret_cast<float4*>(out + off + lead);
            const unsigned b = lead;                  // smem shift 0..3

            if (b == 0u) {
                const float4* sp = reinterpret_cast<const float4*>(sb);
                for (unsigned k = lane; k < n4; k += 32u)
                    st_cs(vd + k, sp[k]);
            } else if (b == 2u) {
                const float2* sp = reinterpret_cast<const float2*>(sb + 2u);
                for (unsigned k = lane; k < n4; k += 32u) {
                    float2 x = sp[2u * k];
                    float2 y = sp[2u * k + 1u];
                    float4 R; R.x = x.x; R.y = x.y; R.z = y.x; R.w = y.y;
                    st_cs(vd + k, R);
                }
            } else {
                const float* sp = sb + b;
                for (unsigned k = lane; k < n4; k += 32u) {
                    unsigned e = 4u * k;
                    float4 R;
                    R.x = sp[e]; R.y = sp[e + 1u]; R.z = sp[e + 2u]; R.w = sp[e + 3u];
                    st_cs(vd + k, R);
                }
            }

            const unsigned done = lead + (n4 << 2);   // tail (<4 elems)
            if (lane < olen - done) out[off + done + lane] = sb[done + lane];
        }

        __syncthreads();   // all reads of cur done before restage
        cur ^= 1u;
        ci = ni; cr = nr; cc0 = nc0; clen = nlen;
    }
}

extern "C" void kernel_launch(void* const* d_in, const int* in_sizes, int n_in,
                              void* d_out, int out_size) {
    const float* mask = (const float*)d_in[0];
    const int* seq = (const int*)d_in[1];
    const int* nh = (n_in >= 3) ? (const int*)d_in[2] : nullptr;

    int B = in_sizes[1];
    if (B > MAXB) B = MAXB;
    long long SS = (long long)in_sizes[0] / (B > 0 ? B : 1);
    unsigned S = (unsigned)(sqrt((double)SS) + 0.5);

    if (out_size <= 0) return;
    fused_kernel<<<NCTA, TPB>>>(mask, seq, nh, (float*)d_out,
                                (unsigned)out_size, S, B);
}

// round 13
// speedup vs baseline: 1.2656x; 1.2656x over previous
#include <cuda_runtime.h>
#include <stdint.h>
#include <math.h>

#define MAXB 16
#define MAXH 32
#define TPB 256
#define NWARP (TPB / 32)
#define NCTA 1480
#define SBUF_N 2064   // max row (2047) + window slack, 16B-multiple

__device__ unsigned g_ctr;   // work-steal ticket counter

__global__ void reset_ctr() { g_ctr = NCTA; }

__device__ __forceinline__ void st_cs(float4* p, float4 v) {
    asm volatile("st.global.cs.v4.f32 [%0], {%1,%2,%3,%4};"
                 :: "l"(p), "f"(v.x), "f"(v.y), "f"(v.z), "f"(v.w) : "memory");
}
__device__ __forceinline__ void cp_async16(unsigned saddr, const void* gptr) {
    asm volatile("cp.async.ca.shared.global [%0], [%1], 16;"
                 :: "r"(saddr), "l"(gptr));
}
#define CP_COMMIT() asm volatile("cp.async.commit_group;" ::: "memory")
#define CP_WAIT(n)  asm volatile("cp.async.wait_group %0;" :: "n"(n) : "memory")

// Fused persistent kernel, double-buffered, WORK-STEALING over source rows.
// CTA: stage row in SMEM via cp.async (overlapped with previous row's
// fan-out), then warp-per-head fan-out to all H destinations.
__global__ void __launch_bounds__(TPB)
fused_kernel(const float* __restrict__ mask, const int* __restrict__ seq,
             const int* __restrict__ nh, float* __restrict__ out,
             unsigned out_size, unsigned S, int B) {
    __shared__ unsigned sh_s[MAXB];
    __shared__ unsigned sh_boff[MAXB + 1];
    __shared__ unsigned sh_rp[MAXB + 1];
    __shared__ unsigned sh_H, sh_rows;
    __shared__ unsigned sh_next;
    __shared__ __align__(16) float sbuf[2][SBUF_N];

    const unsigned t = threadIdx.x;
    const unsigned lane = t & 31u;
    const unsigned wid  = t >> 5;

    if (t < (unsigned)B) sh_s[t] = (unsigned)seq[t];
    if (t == 0) {
        unsigned H = nh ? (unsigned)(*nh) : 16u;
        if (H > MAXH) H = MAXH;
        if (H < 1u) H = 1u;
        sh_H = H;
    }
    __syncthreads();
    if (t == 0) {
        unsigned acc = 0, racc = 0, H = sh_H;
        for (int i = 0; i < B; ++i) {
            unsigned s = sh_s[i];
            sh_boff[i] = acc;
            sh_rp[i] = racc;
            acc += H * s * s;
            racc += s;
        }
        sh_boff[B] = acc;
        sh_rp[B] = racc;
        sh_rows = racc;
    }
    __syncthreads();

    const unsigned H = sh_H;
    const unsigned totalRows = sh_rows;

    auto decode = [&](unsigned w, unsigned& i, unsigned& r, unsigned& s) {
        unsigned ii = 0;
        while (ii + 1u < (unsigned)B && w >= sh_rp[ii + 1u]) ++ii;
        i = ii; r = w - sh_rp[ii]; s = sh_s[ii];
    };
    // stage row (i,r) (+window slack) into sbuf[buf]; row base 16B-aligned;
    // overread <= 1 float4 stays in the mask since r <= S-2.
    auto stage = [&](unsigned buf, unsigned i, unsigned r, unsigned s) {
        const float4* src4 = reinterpret_cast<const float4*>(
            mask + ((size_t)i * S + r) * (size_t)S);
        unsigned sb = (unsigned)__cvta_generic_to_shared(&sbuf[buf][0]);
        const unsigned nld = (s + 7u) >> 2;
        for (unsigned k = t; k < nld; k += TPB)
            cp_async16(sb + 16u * k, src4 + k);
    };

    unsigned w = blockIdx.x;          // first NCTA tickets are implicit
    if (w >= totalRows) return;

    unsigned ci, cr, cs;
    decode(w, ci, cr, cs);
    stage(0, ci, cr, cs);
    CP_COMMIT();
    unsigned cur = 0;

    while (true) {
        // grab next ticket (work-stealing; overlaps nothing critical)
        if (t == 0) sh_next = atomicAdd(&g_ctr, 1u);
        __syncthreads();
        const unsigned wn = sh_next;
        const bool havenext = (wn < totalRows);

        unsigned ni = 0, nr = 0, ns = 0;
        if (havenext) {
            decode(wn, ni, nr, ns);
            stage(cur ^ 1u, ni, nr, ns);   // overlaps fan-out below
            CP_COMMIT();
            CP_WAIT(1);                     // current buffer complete
        } else {
            CP_WAIT(0);
        }
        __syncthreads();                    // staged data visible

        const unsigned s2 = cs * cs;
        const unsigned boff = sh_boff[ci];
        const float* sb = sbuf[cur];

        // ---- warp-per-head fan-out of row (ci, cr) ----
        for (unsigned h = wid; h < H; h += NWARP) {
            unsigned off = boff + h * s2 + cr * cs;
            if (off >= out_size) continue;
            unsigned len = cs;
            if (len > out_size - off) len = out_size - off;

            unsigned lead = (4u - (off & 3u)) & 3u;   // align dst to 16B
            if (lead > len) lead = len;
            if (lane < lead) out[off + lane] = sb[lane];

            const unsigned n4 = (len - lead) >> 2;
            float4* vd = reinterpret_cast<float4*>(out + off + lead);
            const unsigned b = lead;                  // smem shift 0..3

            if (b == 0u) {
                const float4* sp = reinterpret_cast<const float4*>(sb);
                for (unsigned k = lane; k < n4; k += 32u)
                    st_cs(vd + k, sp[k]);
            } else if (b == 2u) {
                const float2* sp = reinterpret_cast<const float2*>(sb + 2u);
                for (unsigned k = lane; k < n4; k += 32u) {
                    float2 x = sp[2u * k];
                    float2 y = sp[2u * k + 1u];
                    float4 R; R.x = x.x; R.y = x.y; R.z = y.x; R.w = y.y;
                    st_cs(vd + k, R);
                }
            } else {
                const float* sp = sb + b;
                for (unsigned k = lane; k < n4; k += 32u) {
                    unsigned e = 4u * k;
                    float4 R;
                    R.x = sp[e]; R.y = sp[e + 1u]; R.z = sp[e + 2u]; R.w = sp[e + 3u];
                    st_cs(vd + k, R);
                }
            }

            const unsigned done = lead + (n4 << 2);   // tail (<4 elems)
            if (lane < len - done) out[off + done + lane] = sb[done + lane];
        }

        if (!havenext) break;
        __syncthreads();   // all reads of cur done before restage
        cur ^= 1u;
        ci = ni; cr = nr; cs = ns;
    }
}

extern "C" void kernel_launch(void* const* d_in, const int* in_sizes, int n_in,
                              void* d_out, int out_size) {
    const float* mask = (const float*)d_in[0];
    const int* seq = (const int*)d_in[1];
    const int* nh = (n_in >= 3) ? (const int*)d_in[2] : nullptr;

    int B = in_sizes[1];
    if (B > MAXB) B = MAXB;
    long long SS = (long long)in_sizes[0] / (B > 0 ? B : 1);
    unsigned S = (unsigned)(sqrt((double)SS) + 0.5);

    if (out_size <= 0) return;
    reset_ctr<<<1, 1>>>();
    fused_kernel<<<NCTA, TPB>>>(mask, seq, nh, (float*)d_out,
                                (unsigned)out_size, S, B);
}

// round 14
// speedup vs baseline: 1.3091x; 1.0343x over previous
#include <cuda_runtime.h>
#include <stdint.h>
#include <math.h>

#define MAXB 16
#define MAXH 32
#define TPB 256
#define NCTA 740
#define SBUF_N 2064   // floats: max row (2047) + slack, 16B-multiple

__device__ unsigned g_ctr;
__global__ void reset_ctr() { g_ctr = NCTA; }

__device__ __forceinline__ void cp_async16(unsigned saddr, const void* gptr) {
    asm volatile("cp.async.ca.shared.global [%0], [%1], 16;"
                 :: "r"(saddr), "l"(gptr));
}
#define CP_COMMIT()   asm volatile("cp.async.commit_group;" ::: "memory")
#define CP_WAIT(n)    asm volatile("cp.async.wait_group %0;" :: "n"(n) : "memory")
#define BULK_COMMIT() asm volatile("cp.async.bulk.commit_group;" ::: "memory")
#define BULK_WAIT0()  asm volatile("cp.async.bulk.wait_group 0;" ::: "memory")
#define FENCE_ASYNC() asm volatile("fence.proxy.async;" ::: "memory")

__device__ __forceinline__ void bulk_store(float* gdst, unsigned ssrc, unsigned bytes) {
    asm volatile("cp.async.bulk.global.shared::cta.bulk_group [%0], [%1], %2;"
                 :: "l"(gdst), "r"(ssrc), "r"(bytes) : "memory");
}

// Persistent, work-stealing, double-buffered staging. Fan-out uses TMA bulk
// stores (SMEM -> GMEM), bypassing the per-warp STG.128 issue cap. Up to 3
// shifted SMEM copies give every head a 16B-aligned bulk source.
__global__ void __launch_bounds__(TPB)
fused_kernel(const float* __restrict__ mask, const int* __restrict__ seq,
             const int* __restrict__ nh, float* __restrict__ out,
             unsigned out_size, unsigned S, int B) {
    __shared__ unsigned sh_s[MAXB];
    __shared__ unsigned sh_boff[MAXB];
    __shared__ unsigned sh_rp[MAXB + 1];
    __shared__ unsigned sh_H, sh_rows, sh_next;
    __shared__ __align__(16) float cbuf[2][SBUF_N];   // canonical row, dbl-buffered
    __shared__ __align__(16) float shbuf[3][SBUF_N];  // shifts 1..3

    const unsigned t = threadIdx.x;

    if (t < (unsigned)B) sh_s[t] = (unsigned)seq[t];
    if (t == 0) {
        unsigned H = nh ? (unsigned)(*nh) : 16u;
        if (H > MAXH) H = MAXH;
        if (H < 1u) H = 1u;
        sh_H = H;
    }
    __syncthreads();
    if (t == 0) {
        unsigned acc = 0, racc = 0, H = sh_H;
        for (int i = 0; i < B; ++i) {
            unsigned s = sh_s[i];
            sh_boff[i] = acc;
            sh_rp[i] = racc;
            acc += H * s * s;
            racc += s;
        }
        sh_rp[B] = racc;
        sh_rows = racc;
    }
    __syncthreads();

    const unsigned H = sh_H;
    const unsigned totalRows = sh_rows;

    auto decode = [&](unsigned w, unsigned& i, unsigned& r, unsigned& s) {
        unsigned ii = 0;
        while (ii + 1u < (unsigned)B && w >= sh_rp[ii + 1u]) ++ii;
        i = ii; r = w - sh_rp[ii]; s = sh_s[ii];
    };
    // stage row (i,r)+slack; row base 16B-aligned; overread stays in mask (r <= S-2)
    auto stage = [&](unsigned buf, unsigned i, unsigned r, unsigned s) {
        const float4* src4 = reinterpret_cast<const float4*>(
            mask + ((size_t)i * S + r) * (size_t)S);
        unsigned sb = (unsigned)__cvta_generic_to_shared(&cbuf[buf][0]);
        const unsigned nld = (s + 7u) >> 2;
        for (unsigned k = t; k < nld; k += TPB)
            cp_async16(sb + 16u * k, src4 + k);
    };

    unsigned w = blockIdx.x;
    if (w >= totalRows) return;

    unsigned ci, cr, cs;
    decode(w, ci, cr, cs);
    stage(0, ci, cr, cs);
    CP_COMMIT();
    unsigned cur = 0;

    while (true) {
        if (t == 0) sh_next = atomicAdd(&g_ctr, 1u);
        BULK_WAIT0();        // prior row's bulk reads of cbuf/shbuf complete
        __syncthreads();     // publishes sh_next; orders bulk-wait CTA-wide

        const unsigned wn = sh_next;
        const bool havenext = (wn < totalRows);
        unsigned ni = 0, nr = 0, ns = 0;
        if (havenext) {
            decode(wn, ni, nr, ns);
            stage(cur ^ 1u, ni, nr, ns);
            CP_COMMIT();
            CP_WAIT(1);      // current canonical buffer complete
        } else {
            CP_WAIT(0);
        }
        __syncthreads();     // cbuf[cur] visible CTA-wide

        const unsigned s2 = cs * cs;
        const unsigned base = sh_boff[ci] + cr * cs;
        const float* cb = cbuf[cur];

        // which shifts occur? pattern of (base + h*s2) mod 4 has period <= 4 in h
        unsigned need = 0;
        const unsigned hprobe = (H < 4u) ? H : 4u;
        for (unsigned hh = 0; hh < hprobe; ++hh) {
            unsigned lead = (4u - ((base + hh * s2) & 3u)) & 3u;
            if (lead) need |= 1u << (lead - 1u);
        }
        // build shifted copies: shbuf[b-1][k] = cb[k+b]
        const unsigned nb4 = (cs + 3u) >> 2;
        for (unsigned b = 1; b <= 3u; ++b) {
            if (!((need >> (b - 1u)) & 1u)) continue;
            float4* d4 = reinterpret_cast<float4*>(shbuf[b - 1u]);
            for (unsigned k = t; k < nb4; k += TPB) {
                unsigned e = 4u * k + b;   // reads <= cs+6 < SBUF_N (garbage ok)
                float4 R;
                R.x = cb[e]; R.y = cb[e + 1u]; R.z = cb[e + 2u]; R.w = cb[e + 3u];
                d4[k] = R;
            }
        }
        __syncthreads();     // shifted copies visible

        if (t < 32u) {       // warp 0 issues bulk stores
            FENCE_ASYNC();   // generic-proxy STS -> async-proxy TMA reads
            for (unsigned h = t; h < H; h += 32u) {
                unsigned off = base + h * s2;
                if (off >= out_size) continue;
                unsigned len = cs;
                if (len > out_size - off) len = out_size - off;
                unsigned lead = (4u - (off & 3u)) & 3u;
                if (lead > len) lead = len;
                unsigned n4 = (len - lead) >> 2;
                if (n4) {
                    const float* sp = lead ? shbuf[lead - 1u] : cb;
                    bulk_store(out + off + lead,
                               (unsigned)__cvta_generic_to_shared(sp),
                               n4 * 16u);
                }
            }
        }
        BULK_COMMIT();       // uniform: per-thread group (empty for non-issuers)

        if (t >= 128u) {     // scalar head (<4) + tail (<4) per head
            const unsigned idx = t - 128u;
            const unsigned e = idx & 7u;
            for (unsigned h = idx >> 3; h < H; h += 16u) {
                unsigned off = base + h * s2;
                if (off >= out_size) continue;
                unsigned len = cs;
                if (len > out_size - off) len = out_size - off;
                unsigned lead = (4u - (off & 3u)) & 3u;
                if (lead > len) lead = len;
                unsigned done = lead + (((len - lead) >> 2) << 2);
                if (e < 4u) {
                    if (e < lead) out[off + e] = cb[e];
                } else {
                    unsigned e2 = e - 4u;
                    if (e2 < len - done) out[off + done + e2] = cb[done + e2];
                }
            }
        }

        if (!havenext) { BULK_WAIT0(); break; }
        cur ^= 1u;
        ci = ni; cr = nr; cs = ns;
    }
}

extern "C" void kernel_launch(void* const* d_in, const int* in_sizes, int n_in,
                              void* d_out, int out_size) {
    const float* mask = (const float*)d_in[0];
    const int* seq = (const int*)d_in[1];
    const int* nh = (n_in >= 3) ? (const int*)d_in[2] : nullptr;

    int B = in_sizes[1];
    if (B > MAXB) B = MAXB;
    long long SS = (long long)in_sizes[0] / (B > 0 ? B : 1);
    unsigned S = (unsigned)(sqrt((double)SS) + 0.5);

    if (out_size <= 0) return;
    reset_ctr<<<1, 1>>>();
    fused_kernel<<<NCTA, TPB>>>(mask, seq, nh, (float*)d_out,
                                (unsigned)out_size, S, B);
}